// round 5
// baseline (speedup 1.0000x reference)
#include <cuda_runtime.h>

// Problem constants (fixed by setup_inputs)
#define NNODES 32768
#define DIM    128
#define NH     4
#define HD     512      // NH*DIM
#define NEDGE  262144
#define NGRAPH 8
#define NPG    4096
#define NCH    16       // chunks per (b,h) for KV partials
#define CHN    256      // nodes per chunk (NPG/NCH)

// ----------------------------- scratch (static device globals) ---------------
__device__ float g_qs  [NNODES*HD];
__device__ float g_ks  [NNODES*HD];
__device__ float g_cur0[NNODES*HD];
__device__ float g_cur1[NNODES*HD];
__device__ float g_acc [NNODES*HD];
__device__ float g_tmp [NNODES*HD];
__device__ float g_kvt [32*16384];        // KV^T per (b,h): [e][d]
__device__ float g_pkv [NCH*32*16384];    // KV partials per chunk
__device__ float g_pv  [NCH*4096];        // vsum partials
__device__ float g_vsum[4096];
__device__ float g_ksp [NCH*4096];        // ksum partials
__device__ float g_ksum[4096];
__device__ float g_invden[NNODES*NH];
__device__ float g_dis [NNODES];
__device__ float g_w   [NEDGE];
__device__ int   g_cnt [NNODES];
__device__ int   g_rowptr[NNODES+1];
__device__ int   g_fill[NNODES];
__device__ int   g_bsum[NNODES/256];
__device__ int   g_col [NEDGE];
__device__ int   g_ekey[NEDGE];

// ----------------------------- generic tiled GEMM: C = scale*(A*B^T + bias) --
// A[M,K] lda, B[Nc,K] ldb (row-major), C[M,Nc] ldc. 128x128 tile per block,
// 256 threads, 8x8 micro-tile. Batched over blockIdx.z with (b,h) split strides.
__global__ void gemm_abT(const float* __restrict__ A, int lda, long sOutA, long sInA,
                         const float* __restrict__ Bm, int ldb, long sOutB, long sInB,
                         const float* __restrict__ bias,
                         float* __restrict__ C, int ldc, long sOutC, long sInC,
                         int K, float scale)
{
    __shared__ float As[32][132];
    __shared__ float Bs[32][132];
    int z = blockIdx.z; int zb = z >> 2, zh = z & 3;
    const float* Ab = A  + zb*sOutA + zh*sInA;
    const float* Bb = Bm + zb*sOutB + zh*sInB;
    float*       Cb = C  + zb*sOutC + zh*sInC;
    int i0 = blockIdx.x * 128, j0 = blockIdx.y * 128;
    int tid = threadIdx.x, ty = tid >> 4, tx = tid & 15;

    float acc[8][8];
#pragma unroll
    for (int a = 0; a < 8; a++)
#pragma unroll
        for (int b = 0; b < 8; b++) acc[a][b] = 0.f;

    for (int kt = 0; kt < K; kt += 32) {
#pragma unroll
        for (int r = 0; r < 4; r++) {
            int idx = tid + r * 256;         // 0..1023
            int row = idx >> 3;              // 0..127
            int kq  = (idx & 7) * 4;         // 0..28
            float4 v = *(const float4*)&Ab[(long)(i0 + row) * lda + kt + kq];
            As[kq][row] = v.x; As[kq+1][row] = v.y; As[kq+2][row] = v.z; As[kq+3][row] = v.w;
            float4 w = *(const float4*)&Bb[(long)(j0 + row) * ldb + kt + kq];
            Bs[kq][row] = w.x; Bs[kq+1][row] = w.y; Bs[kq+2][row] = w.z; Bs[kq+3][row] = w.w;
        }
        __syncthreads();
#pragma unroll
        for (int kk = 0; kk < 32; kk++) {
            float a[8], b[8];
#pragma unroll
            for (int ii = 0; ii < 8; ii++) a[ii] = As[kk][ty*8 + ii];
#pragma unroll
            for (int jj = 0; jj < 8; jj++) b[jj] = Bs[kk][tx*8 + jj];
#pragma unroll
            for (int ii = 0; ii < 8; ii++)
#pragma unroll
                for (int jj = 0; jj < 8; jj++) acc[ii][jj] += a[ii] * b[jj];
        }
        __syncthreads();
    }
#pragma unroll
    for (int ii = 0; ii < 8; ii++) {
        int row = i0 + ty*8 + ii;
#pragma unroll
        for (int jj = 0; jj < 8; jj += 4) {
            int colj = j0 + tx*8 + jj;
            float4 o;
            o.x = scale * (acc[ii][jj+0] + (bias ? bias[colj+0] : 0.f));
            o.y = scale * (acc[ii][jj+1] + (bias ? bias[colj+1] : 0.f));
            o.z = scale * (acc[ii][jj+2] + (bias ? bias[colj+2] : 0.f));
            o.w = scale * (acc[ii][jj+3] + (bias ? bias[colj+3] : 0.f));
            *(float4*)&Cb[(long)row * ldc + colj] = o;
        }
    }
}

// ----------------------------- normalize q,k rows per (node, head) -----------
__global__ void normalize_qk_kernel()
{
    int i = blockIdx.x;
    int h = threadIdx.x >> 5, l = threadIdx.x & 31;
    long base = (long)i * HD + h * DIM + l * 4;
    float4 q = *(float4*)&g_qs[base];
    float s = q.x*q.x + q.y*q.y + q.z*q.z + q.w*q.w;
#pragma unroll
    for (int o = 16; o; o >>= 1) s += __shfl_xor_sync(0xffffffffu, s, o);
    float r = rsqrtf(s);
    q.x *= r; q.y *= r; q.z *= r; q.w *= r;
    *(float4*)&g_qs[base] = q;

    float4 k = *(float4*)&g_ks[base];
    s = k.x*k.x + k.y*k.y + k.z*k.z + k.w*k.w;
#pragma unroll
    for (int o = 16; o; o >>= 1) s += __shfl_xor_sync(0xffffffffu, s, o);
    r = rsqrtf(s);
    k.x *= r; k.y *= r; k.z *= r; k.w *= r;
    *(float4*)&g_ks[base] = k;
}

// ----------------------------- ksum partials ---------------------------------
__global__ void ksum_partial_kernel()
{
    int chunk = blockIdx.x, bh = blockIdx.y;
    int b = bh >> 2, h = bh & 3, d = threadIdx.x;
    long base = ((long)b * NPG + chunk * CHN) * HD + h * DIM + d;
    float s = 0.f;
    for (int n = 0; n < CHN; n++) s += g_ks[base + (long)n * HD];
    g_ksp[(chunk * 32 + bh) * DIM + d] = s;
}

// deterministic fixed-order reduce of 16 chunk partials
__global__ void reduce16(const float* __restrict__ part, float* __restrict__ out, int n)
{
    int i = blockIdx.x * blockDim.x + threadIdx.x;
    if (i < n) {
        float s = 0.f;
#pragma unroll
        for (int c = 0; c < NCH; c++) s += part[(long)c * n + i];
        out[i] = s;
    }
}

// ----------------------------- inverse denominator (loop-invariant) ----------
__global__ void invden_kernel()
{
    int i = blockIdx.x;
    int h = threadIdx.x >> 5, l = threadIdx.x & 31;
    int b = i >> 12;  // /NPG
    float4 q = *(float4*)&g_qs[(long)i * HD + h * DIM + l * 4];
    float4 km = *(float4*)&g_ksum[(b * NH + h) * DIM + l * 4];
    float s = q.x*km.x + q.y*km.y + q.z*km.z + q.w*km.w;
#pragma unroll
    for (int o = 16; o; o >>= 1) s += __shfl_xor_sync(0xffffffffu, s, o);
    if (l == 0) g_invden[i * NH + h] = 1.f / (s + (float)NPG);
}

// ----------------------------- graph prep ------------------------------------
__global__ void count_kernel(const int* __restrict__ ei)
{
    int e = blockIdx.x * blockDim.x + threadIdx.x;
    if (e < NEDGE) atomicAdd(&g_cnt[ei[e]], 1);
}

__global__ void scan1_kernel()
{
    __shared__ int sh[256];
    int tid = threadIdx.x;
    int i = blockIdx.x * 256 + tid;
    int v = g_cnt[i];
    sh[tid] = v;
    __syncthreads();
    for (int o = 1; o < 256; o <<= 1) {
        int t = (tid >= o) ? sh[tid - o] : 0;
        __syncthreads();
        sh[tid] += t;
        __syncthreads();
    }
    g_rowptr[i] = sh[tid] - v;                 // block-local exclusive
    if (tid == 255) g_bsum[blockIdx.x] = sh[255];
}

__global__ void scan2_kernel()
{
    __shared__ int sh[128];
    int tid = threadIdx.x;
    int v = g_bsum[tid];
    sh[tid] = v;
    __syncthreads();
    for (int o = 1; o < 128; o <<= 1) {
        int t = (tid >= o) ? sh[tid - o] : 0;
        __syncthreads();
        sh[tid] += t;
        __syncthreads();
    }
    g_bsum[tid] = sh[tid] - v;                 // exclusive block offsets
}

__global__ void scan3_kernel()
{
    int tid = threadIdx.x;
    int i = blockIdx.x * 256 + tid;
    g_rowptr[i] += g_bsum[blockIdx.x];
    int c = g_cnt[i];
    g_dis[i] = (c > 0) ? rsqrtf((float)c) : 0.f;
    if (i == 0) g_rowptr[NNODES] = NEDGE;
}

__global__ void scatter_kernel(const int* __restrict__ ei)
{
    int e = blockIdx.x * blockDim.x + threadIdx.x;
    if (e < NEDGE) {
        int r = ei[e], c = ei[NEDGE + e];
        int p = g_rowptr[r] + atomicAdd(&g_fill[r], 1);
        g_col[p] = c;
        g_ekey[p] = e;
    }
}

// canonicalize per-row edge order (determinism) + edge weights
__global__ void sortw_kernel()
{
    int i = blockIdx.x * blockDim.x + threadIdx.x;
    if (i >= NNODES) return;
    int s = g_rowptr[i], t = g_rowptr[i + 1];
    int n = t - s;
    float di = g_dis[i];
    if (n > 1 && n <= 64) {
        int kk[64], cc[64];
        for (int j = 0; j < n; j++) { kk[j] = g_ekey[s + j]; cc[j] = g_col[s + j]; }
        for (int a = 1; a < n; a++) {
            int kvv = kk[a], cv = cc[a], b = a - 1;
            while (b >= 0 && kk[b] > kvv) { kk[b+1] = kk[b]; cc[b+1] = cc[b]; b--; }
            kk[b+1] = kvv; cc[b+1] = cv;
        }
        for (int j = 0; j < n; j++) { g_col[s + j] = cc[j]; g_w[s + j] = di * g_dis[cc[j]]; }
    } else {
        for (int j = 0; j < n; j++) g_w[s + j] = di * g_dis[g_col[s + j]];
    }
}

// ----------------------------- init cur = acc = broadcast(x) -----------------
__global__ void init_kernel(const float* __restrict__ x)
{
    long gid = (long)blockIdx.x * blockDim.x + threadIdx.x;  // float4 index
    long f = gid * 4;
    int i = (int)(f >> 9);
    int d = (int)(f & 127);
    float4 v = *(const float4*)&x[(long)i * DIM + d];
    *(float4*)&g_cur0[f] = v;
    *(float4*)&g_acc[f]  = v;
}

// ----------------------------- per-iter: KV^T partials + vsum partials -------
__global__ void kv_partial_kernel(const float* __restrict__ cur)
{
    __shared__ float CU[16][128];
    __shared__ float KS[16][128];
    int chunk = blockIdx.x, bh = blockIdx.y;
    int b = bh >> 2, h = bh & 3;
    long nodeBase = (long)b * NPG + chunk * CHN;
    int tid = threadIdx.x, ty = tid >> 4, tx = tid & 15;

    float acc[8][8];
#pragma unroll
    for (int a = 0; a < 8; a++)
#pragma unroll
        for (int c = 0; c < 8; c++) acc[a][c] = 0.f;
    float vs = 0.f;

    for (int t0 = 0; t0 < CHN; t0 += 16) {
#pragma unroll
        for (int r = 0; r < 2; r++) {
            int idx = tid + r * 256;          // 0..511
            int nn = idx >> 5;                // 0..15
            int c4 = (idx & 31) * 4;          // 0..124
            long off = (nodeBase + t0 + nn) * HD + h * DIM + c4;
            *(float4*)&CU[nn][c4] = *(const float4*)&cur[off];
            *(float4*)&KS[nn][c4] = *(const float4*)&g_ks[off];
        }
        __syncthreads();
#pragma unroll
        for (int nn = 0; nn < 16; nn++) {
            float a[8], bv[8];
#pragma unroll
            for (int ii = 0; ii < 8; ii++) a[ii] = CU[nn][ty*8 + ii];   // e-dim
#pragma unroll
            for (int jj = 0; jj < 8; jj++) bv[jj] = KS[nn][tx*8 + jj];  // d-dim
#pragma unroll
            for (int ii = 0; ii < 8; ii++)
#pragma unroll
                for (int jj = 0; jj < 8; jj++) acc[ii][jj] += a[ii] * bv[jj];
        }
        if (tid < 128) {
#pragma unroll
            for (int nn = 0; nn < 16; nn++) vs += CU[nn][tid];
        }
        __syncthreads();
    }
    long base = ((long)chunk * 32 + bh) * 16384;
#pragma unroll
    for (int ii = 0; ii < 8; ii++) {
#pragma unroll
        for (int jj = 0; jj < 8; jj += 4) {
            float4 o;
            o.x = acc[ii][jj]; o.y = acc[ii][jj+1]; o.z = acc[ii][jj+2]; o.w = acc[ii][jj+3];
            *(float4*)&g_pkv[base + (ty*8 + ii) * 128 + tx*8 + jj] = o;
        }
    }
    if (tid < 128) g_pv[(chunk * 32 + bh) * 128 + tid] = vs;
}

// ----------------------------- per-iter: GCN gather + attn combine + acc -----
__global__ void fuse_kernel(const float* __restrict__ cur, float* __restrict__ curn)
{
    int slot = threadIdx.x >> 6;       // 4 nodes per block
    int t = threadIdx.x & 63;          // 64 threads per node
    int i = blockIdx.x * 4 + slot;
    int b = i >> 12;
    int f0 = t * 4, f1 = t * 4 + 256;
    int s = g_rowptr[i], e = g_rowptr[i + 1];

    float4 gg0 = make_float4(0,0,0,0), gg1 = make_float4(0,0,0,0);
    for (int p = s; p < e; p++) {
        int c = g_col[p]; float w = g_w[p];
        const float* cr = cur + (long)c * HD;
        float4 a0 = *(const float4*)&cr[f0];
        float4 a1 = *(const float4*)&cr[f1];
        gg0.x += w * a0.x; gg0.y += w * a0.y; gg0.z += w * a0.z; gg0.w += w * a0.w;
        gg1.x += w * a1.x; gg1.y += w * a1.y; gg1.z += w * a1.z; gg1.w += w * a1.w;
    }
    int h0 = f0 >> 7, h1 = f1 >> 7;
    float id0 = g_invden[i * NH + h0];
    float id1 = g_invden[i * NH + h1];
    long ib = (long)i * HD;
    float4 t0 = *(const float4*)&g_tmp[ib + f0];
    float4 t1 = *(const float4*)&g_tmp[ib + f1];
    float4 v0 = *(const float4*)&g_vsum[(b * NH + h0) * DIM + (f0 & 127)];
    float4 v1 = *(const float4*)&g_vsum[(b * NH + h1) * DIM + (f1 & 127)];

    float4 r0, r1;
    r0.x = 0.5f*gg0.x + 0.5f*((t0.x + v0.x) * id0);
    r0.y = 0.5f*gg0.y + 0.5f*((t0.y + v0.y) * id0);
    r0.z = 0.5f*gg0.z + 0.5f*((t0.z + v0.z) * id0);
    r0.w = 0.5f*gg0.w + 0.5f*((t0.w + v0.w) * id0);
    r1.x = 0.5f*gg1.x + 0.5f*((t1.x + v1.x) * id1);
    r1.y = 0.5f*gg1.y + 0.5f*((t1.y + v1.y) * id1);
    r1.z = 0.5f*gg1.z + 0.5f*((t1.z + v1.z) * id1);
    r1.w = 0.5f*gg1.w + 0.5f*((t1.w + v1.w) * id1);

    *(float4*)&curn[ib + f0] = r0;
    *(float4*)&curn[ib + f1] = r1;

    float4 a0 = *(float4*)&g_acc[ib + f0];
    a0.x += r0.x; a0.y += r0.y; a0.z += r0.z; a0.w += r0.w;
    *(float4*)&g_acc[ib + f0] = a0;
    float4 a1 = *(float4*)&g_acc[ib + f1];
    a1.x += r1.x; a1.y += r1.y; a1.z += r1.z; a1.w += r1.w;
    *(float4*)&g_acc[ib + f1] = a1;
}

// ----------------------------- host orchestration ----------------------------
extern "C" void kernel_launch(void* const* d_in, const int* in_sizes, int n_in,
                              void* d_out, int out_size)
{
    const float* x    = (const float*)d_in[0];
    const float* Wq_w = (const float*)d_in[1];
    const float* Wq_b = (const float*)d_in[2];
    const float* Wk_w = (const float*)d_in[3];
    const float* Wk_b = (const float*)d_in[4];
    const float* Wo_w = (const float*)d_in[5];
    const float* Wo_b = (const float*)d_in[6];
    const int*   ei   = (const int*)  d_in[7];
    float* out = (float*)d_out;

    float *qs, *ks, *cur0, *cur1, *acc, *tmp, *kvt, *pkv, *pv, *vsum, *ksp, *ksum;
    int *cnt, *fill;
    cudaGetSymbolAddress((void**)&qs,   g_qs);
    cudaGetSymbolAddress((void**)&ks,   g_ks);
    cudaGetSymbolAddress((void**)&cur0, g_cur0);
    cudaGetSymbolAddress((void**)&cur1, g_cur1);
    cudaGetSymbolAddress((void**)&acc,  g_acc);
    cudaGetSymbolAddress((void**)&tmp,  g_tmp);
    cudaGetSymbolAddress((void**)&kvt,  g_kvt);
    cudaGetSymbolAddress((void**)&pkv,  g_pkv);
    cudaGetSymbolAddress((void**)&pv,   g_pv);
    cudaGetSymbolAddress((void**)&vsum, g_vsum);
    cudaGetSymbolAddress((void**)&ksp,  g_ksp);
    cudaGetSymbolAddress((void**)&ksum, g_ksum);
    cudaGetSymbolAddress((void**)&cnt,  g_cnt);
    cudaGetSymbolAddress((void**)&fill, g_fill);

    // Q/K projections: [32768,512] = x[32768,128] @ W^T + b
    gemm_abT<<<dim3(256,4,1),256>>>(x, DIM, 0, 0, Wq_w, DIM, 0, 0, Wq_b, qs, HD, 0, 0, DIM, 1.f);
    gemm_abT<<<dim3(256,4,1),256>>>(x, DIM, 0, 0, Wk_w, DIM, 0, 0, Wk_b, ks, HD, 0, 0, DIM, 1.f);
    normalize_qk_kernel<<<NNODES,128>>>();
    ksum_partial_kernel<<<dim3(NCH,32),128>>>();
    reduce16<<<16,256>>>(ksp, ksum, 4096);
    invden_kernel<<<NNODES,128>>>();

    // Graph prep: degrees, CSR, normalized weights (deterministic order)
    cudaMemsetAsync(cnt,  0, NNODES * sizeof(int));
    cudaMemsetAsync(fill, 0, NNODES * sizeof(int));
    count_kernel<<<NEDGE/256,256>>>(ei);
    scan1_kernel<<<NNODES/256,256>>>();
    scan2_kernel<<<1,128>>>();
    scan3_kernel<<<NNODES/256,256>>>();
    scatter_kernel<<<NEDGE/256,256>>>(ei);
    sortw_kernel<<<NNODES/128,128>>>();

    // cur = acc = broadcast(x) over heads
    init_kernel<<<16384,256>>>(x);

    float* curA = cur0; float* curB = cur1;
    for (int it = 0; it < 4; it++) {
        kv_partial_kernel<<<dim3(NCH,32),256>>>(curA);
        reduce16<<<2048,256>>>(pkv, kvt, 32*16384);
        reduce16<<<16,256>>>(pv, vsum, 4096);
        // tmp[n, h*128+e] = qs[n, h*128+:] @ KV  (batched over 32 (b,h))
        gemm_abT<<<dim3(32,1,32),256>>>(qs, HD, (long)NPG*HD, DIM,
                                        kvt, DIM, 4L*16384, 16384,
                                        nullptr,
                                        tmp, HD, (long)NPG*HD, DIM,
                                        DIM, 1.f);
        fuse_kernel<<<NNODES/4,256>>>(curA, curB);
        float* sw = curA; curA = curB; curB = sw;
    }

    // out = (acc @ Wo^T + Wo_b) / H
    gemm_abT<<<dim3(256,1,1),256>>>(acc, HD, 0, 0, Wo_w, HD, 0, 0, Wo_b,
                                    out, DIM, 0, 0, HD, 0.25f);
    (void)in_sizes; (void)n_in; (void)out_size;
}

// round 6
// speedup vs baseline: 1.0005x; 1.0005x over previous
#include <cuda_runtime.h>

// Problem constants (fixed by setup_inputs)
#define NNODES 32768
#define DIM    128
#define NH     4
#define HD     512      // NH*DIM
#define NEDGE  262144
#define NGRAPH 8
#define NPG    4096
#define NCH    16       // chunks per (b,h) for KV partials
#define CHN    256      // nodes per chunk (NPG/NCH)

// ----------------------------- scratch (static device globals) ---------------
__device__ float g_qs  [NNODES*HD];
__device__ float g_ks  [NNODES*HD];
__device__ float g_cur0[NNODES*HD];
__device__ float g_cur1[NNODES*HD];
__device__ float g_acc [NNODES*HD];
__device__ float g_tmp [NNODES*HD];
__device__ float g_kvt [32*16384];        // KV^T per (b,h): [e][d]
__device__ float g_pkv [NCH*32*16384];    // KV partials per chunk
__device__ float g_pv  [NCH*4096];        // vsum partials
__device__ float g_vsum[4096];
__device__ float g_ksp [NCH*4096];        // ksum partials
__device__ float g_ksum[4096];
__device__ float g_invden[NNODES*NH];
__device__ float g_dis [NNODES];
__device__ float g_w   [NEDGE];
__device__ int   g_cnt [NNODES];
__device__ int   g_rowptr[NNODES+1];
__device__ int   g_fill[NNODES];
__device__ int   g_bsum[NNODES/256];
__device__ int   g_col [NEDGE];
__device__ int   g_ekey[NEDGE];

// ----------------------------- generic tiled GEMM: C = scale*(A*B^T + bias) --
// A[M,K] lda, B[Nc,K] ldb (row-major), C[M,Nc] ldc. 128x128 tile per block,
// 256 threads, 8x8 micro-tile. Batched over blockIdx.z with (b,h) split strides.
__global__ void gemm_abT(const float* __restrict__ A, int lda, long sOutA, long sInA,
                         const float* __restrict__ Bm, int ldb, long sOutB, long sInB,
                         const float* __restrict__ bias,
                         float* __restrict__ C, int ldc, long sOutC, long sInC,
                         int K, float scale)
{
    __shared__ float As[32][132];
    __shared__ float Bs[32][132];
    int z = blockIdx.z; int zb = z >> 2, zh = z & 3;
    const float* Ab = A  + zb*sOutA + zh*sInA;
    const float* Bb = Bm + zb*sOutB + zh*sInB;
    float*       Cb = C  + zb*sOutC + zh*sInC;
    int i0 = blockIdx.x * 128, j0 = blockIdx.y * 128;
    int tid = threadIdx.x, ty = tid >> 4, tx = tid & 15;

    float acc[8][8];
#pragma unroll
    for (int a = 0; a < 8; a++)
#pragma unroll
        for (int b = 0; b < 8; b++) acc[a][b] = 0.f;

    for (int kt = 0; kt < K; kt += 32) {
#pragma unroll
        for (int r = 0; r < 4; r++) {
            int idx = tid + r * 256;         // 0..1023
            int row = idx >> 3;              // 0..127
            int kq  = (idx & 7) * 4;         // 0..28
            float4 v = *(const float4*)&Ab[(long)(i0 + row) * lda + kt + kq];
            As[kq][row] = v.x; As[kq+1][row] = v.y; As[kq+2][row] = v.z; As[kq+3][row] = v.w;
            float4 w = *(const float4*)&Bb[(long)(j0 + row) * ldb + kt + kq];
            Bs[kq][row] = w.x; Bs[kq+1][row] = w.y; Bs[kq+2][row] = w.z; Bs[kq+3][row] = w.w;
        }
        __syncthreads();
#pragma unroll
        for (int kk = 0; kk < 32; kk++) {
            float a[8], b[8];
#pragma unroll
            for (int ii = 0; ii < 8; ii++) a[ii] = As[kk][ty*8 + ii];
#pragma unroll
            for (int jj = 0; jj < 8; jj++) b[jj] = Bs[kk][tx*8 + jj];
#pragma unroll
            for (int ii = 0; ii < 8; ii++)
#pragma unroll
                for (int jj = 0; jj < 8; jj++) acc[ii][jj] += a[ii] * b[jj];
        }
        __syncthreads();
    }
#pragma unroll
    for (int ii = 0; ii < 8; ii++) {
        int row = i0 + ty*8 + ii;
#pragma unroll
        for (int jj = 0; jj < 8; jj += 4) {
            int colj = j0 + tx*8 + jj;
            float4 o;
            o.x = scale * (acc[ii][jj+0] + (bias ? bias[colj+0] : 0.f));
            o.y = scale * (acc[ii][jj+1] + (bias ? bias[colj+1] : 0.f));
            o.z = scale * (acc[ii][jj+2] + (bias ? bias[colj+2] : 0.f));
            o.w = scale * (acc[ii][jj+3] + (bias ? bias[colj+3] : 0.f));
            *(float4*)&Cb[(long)row * ldc + colj] = o;
        }
    }
}

// ----------------------------- normalize q,k rows per (node, head) -----------
__global__ void normalize_qk_kernel()
{
    int i = blockIdx.x;
    int h = threadIdx.x >> 5, l = threadIdx.x & 31;
    long base = (long)i * HD + h * DIM + l * 4;
    float4 q = *(float4*)&g_qs[base];
    float s = q.x*q.x + q.y*q.y + q.z*q.z + q.w*q.w;
#pragma unroll
    for (int o = 16; o; o >>= 1) s += __shfl_xor_sync(0xffffffffu, s, o);
    float r = rsqrtf(s);
    q.x *= r; q.y *= r; q.z *= r; q.w *= r;
    *(float4*)&g_qs[base] = q;

    float4 k = *(float4*)&g_ks[base];
    s = k.x*k.x + k.y*k.y + k.z*k.z + k.w*k.w;
#pragma unroll
    for (int o = 16; o; o >>= 1) s += __shfl_xor_sync(0xffffffffu, s, o);
    r = rsqrtf(s);
    k.x *= r; k.y *= r; k.z *= r; k.w *= r;
    *(float4*)&g_ks[base] = k;
}

// ----------------------------- ksum partials ---------------------------------
__global__ void ksum_partial_kernel()
{
    int chunk = blockIdx.x, bh = blockIdx.y;
    int b = bh >> 2, h = bh & 3, d = threadIdx.x;
    long base = ((long)b * NPG + chunk * CHN) * HD + h * DIM + d;
    float s = 0.f;
    for (int n = 0; n < CHN; n++) s += g_ks[base + (long)n * HD];
    g_ksp[(chunk * 32 + bh) * DIM + d] = s;
}

// deterministic fixed-order reduce of 16 chunk partials
__global__ void reduce16(const float* __restrict__ part, float* __restrict__ out, int n)
{
    int i = blockIdx.x * blockDim.x + threadIdx.x;
    if (i < n) {
        float s = 0.f;
#pragma unroll
        for (int c = 0; c < NCH; c++) s += part[(long)c * n + i];
        out[i] = s;
    }
}

// ----------------------------- inverse denominator (loop-invariant) ----------
__global__ void invden_kernel()
{
    int i = blockIdx.x;
    int h = threadIdx.x >> 5, l = threadIdx.x & 31;
    int b = i >> 12;  // /NPG
    float4 q = *(float4*)&g_qs[(long)i * HD + h * DIM + l * 4];
    float4 km = *(float4*)&g_ksum[(b * NH + h) * DIM + l * 4];
    float s = q.x*km.x + q.y*km.y + q.z*km.z + q.w*km.w;
#pragma unroll
    for (int o = 16; o; o >>= 1) s += __shfl_xor_sync(0xffffffffu, s, o);
    if (l == 0) g_invden[i * NH + h] = 1.f / (s + (float)NPG);
}

// ----------------------------- graph prep ------------------------------------
__global__ void count_kernel(const int* __restrict__ ei)
{
    int e = blockIdx.x * blockDim.x + threadIdx.x;
    if (e < NEDGE) atomicAdd(&g_cnt[ei[e]], 1);
}

__global__ void scan1_kernel()
{
    __shared__ int sh[256];
    int tid = threadIdx.x;
    int i = blockIdx.x * 256 + tid;
    int v = g_cnt[i];
    sh[tid] = v;
    __syncthreads();
    for (int o = 1; o < 256; o <<= 1) {
        int t = (tid >= o) ? sh[tid - o] : 0;
        __syncthreads();
        sh[tid] += t;
        __syncthreads();
    }
    g_rowptr[i] = sh[tid] - v;                 // block-local exclusive
    if (tid == 255) g_bsum[blockIdx.x] = sh[255];
}

__global__ void scan2_kernel()
{
    __shared__ int sh[128];
    int tid = threadIdx.x;
    int v = g_bsum[tid];
    sh[tid] = v;
    __syncthreads();
    for (int o = 1; o < 128; o <<= 1) {
        int t = (tid >= o) ? sh[tid - o] : 0;
        __syncthreads();
        sh[tid] += t;
        __syncthreads();
    }
    g_bsum[tid] = sh[tid] - v;                 // exclusive block offsets
}

__global__ void scan3_kernel()
{
    int tid = threadIdx.x;
    int i = blockIdx.x * 256 + tid;
    g_rowptr[i] += g_bsum[blockIdx.x];
    int c = g_cnt[i];
    g_dis[i] = (c > 0) ? rsqrtf((float)c) : 0.f;
    if (i == 0) g_rowptr[NNODES] = NEDGE;
}

__global__ void scatter_kernel(const int* __restrict__ ei)
{
    int e = blockIdx.x * blockDim.x + threadIdx.x;
    if (e < NEDGE) {
        int r = ei[e], c = ei[NEDGE + e];
        int p = g_rowptr[r] + atomicAdd(&g_fill[r], 1);
        g_col[p] = c;
        g_ekey[p] = e;
    }
}

// canonicalize per-row edge order (determinism) + edge weights
__global__ void sortw_kernel()
{
    int i = blockIdx.x * blockDim.x + threadIdx.x;
    if (i >= NNODES) return;
    int s = g_rowptr[i], t = g_rowptr[i + 1];
    int n = t - s;
    float di = g_dis[i];
    if (n > 1 && n <= 64) {
        int kk[64], cc[64];
        for (int j = 0; j < n; j++) { kk[j] = g_ekey[s + j]; cc[j] = g_col[s + j]; }
        for (int a = 1; a < n; a++) {
            int kvv = kk[a], cv = cc[a], b = a - 1;
            while (b >= 0 && kk[b] > kvv) { kk[b+1] = kk[b]; cc[b+1] = cc[b]; b--; }
            kk[b+1] = kvv; cc[b+1] = cv;
        }
        for (int j = 0; j < n; j++) { g_col[s + j] = cc[j]; g_w[s + j] = di * g_dis[cc[j]]; }
    } else {
        for (int j = 0; j < n; j++) g_w[s + j] = di * g_dis[g_col[s + j]];
    }
}

// ----------------------------- init cur = acc = broadcast(x) -----------------
__global__ void init_kernel(const float* __restrict__ x)
{
    long gid = (long)blockIdx.x * blockDim.x + threadIdx.x;  // float4 index
    long f = gid * 4;
    int i = (int)(f >> 9);
    int d = (int)(f & 127);
    float4 v = *(const float4*)&x[(long)i * DIM + d];
    *(float4*)&g_cur0[f] = v;
    *(float4*)&g_acc[f]  = v;
}

// ----------------------------- per-iter: KV^T partials + vsum partials -------
__global__ void kv_partial_kernel(const float* __restrict__ cur)
{
    __shared__ float CU[16][128];
    __shared__ float KS[16][128];
    int chunk = blockIdx.x, bh = blockIdx.y;
    int b = bh >> 2, h = bh & 3;
    long nodeBase = (long)b * NPG + chunk * CHN;
    int tid = threadIdx.x, ty = tid >> 4, tx = tid & 15;

    float acc[8][8];
#pragma unroll
    for (int a = 0; a < 8; a++)
#pragma unroll
        for (int c = 0; c < 8; c++) acc[a][c] = 0.f;
    float vs = 0.f;

    for (int t0 = 0; t0 < CHN; t0 += 16) {
#pragma unroll
        for (int r = 0; r < 2; r++) {
            int idx = tid + r * 256;          // 0..511
            int nn = idx >> 5;                // 0..15
            int c4 = (idx & 31) * 4;          // 0..124
            long off = (nodeBase + t0 + nn) * HD + h * DIM + c4;
            *(float4*)&CU[nn][c4] = *(const float4*)&cur[off];
            *(float4*)&KS[nn][c4] = *(const float4*)&g_ks[off];
        }
        __syncthreads();
#pragma unroll
        for (int nn = 0; nn < 16; nn++) {
            float a[8], bv[8];
#pragma unroll
            for (int ii = 0; ii < 8; ii++) a[ii] = CU[nn][ty*8 + ii];   // e-dim
#pragma unroll
            for (int jj = 0; jj < 8; jj++) bv[jj] = KS[nn][tx*8 + jj];  // d-dim
#pragma unroll
            for (int ii = 0; ii < 8; ii++)
#pragma unroll
                for (int jj = 0; jj < 8; jj++) acc[ii][jj] += a[ii] * bv[jj];
        }
        if (tid < 128) {
#pragma unroll
            for (int nn = 0; nn < 16; nn++) vs += CU[nn][tid];
        }
        __syncthreads();
    }
    long base = ((long)chunk * 32 + bh) * 16384;
#pragma unroll
    for (int ii = 0; ii < 8; ii++) {
#pragma unroll
        for (int jj = 0; jj < 8; jj += 4) {
            float4 o;
            o.x = acc[ii][jj]; o.y = acc[ii][jj+1]; o.z = acc[ii][jj+2]; o.w = acc[ii][jj+3];
            *(float4*)&g_pkv[base + (ty*8 + ii) * 128 + tx*8 + jj] = o;
        }
    }
    if (tid < 128) g_pv[(chunk * 32 + bh) * 128 + tid] = vs;
}

// ----------------------------- per-iter: GCN gather + attn combine + acc -----
__global__ void fuse_kernel(const float* __restrict__ cur, float* __restrict__ curn)
{
    int slot = threadIdx.x >> 6;       // 4 nodes per block
    int t = threadIdx.x & 63;          // 64 threads per node
    int i = blockIdx.x * 4 + slot;
    int b = i >> 12;
    int f0 = t * 4, f1 = t * 4 + 256;
    int s = g_rowptr[i], e = g_rowptr[i + 1];

    float4 gg0 = make_float4(0,0,0,0), gg1 = make_float4(0,0,0,0);
    for (int p = s; p < e; p++) {
        int c = g_col[p]; float w = g_w[p];
        const float* cr = cur + (long)c * HD;
        float4 a0 = *(const float4*)&cr[f0];
        float4 a1 = *(const float4*)&cr[f1];
        gg0.x += w * a0.x; gg0.y += w * a0.y; gg0.z += w * a0.z; gg0.w += w * a0.w;
        gg1.x += w * a1.x; gg1.y += w * a1.y; gg1.z += w * a1.z; gg1.w += w * a1.w;
    }
    int h0 = f0 >> 7, h1 = f1 >> 7;
    float id0 = g_invden[i * NH + h0];
    float id1 = g_invden[i * NH + h1];
    long ib = (long)i * HD;
    float4 t0 = *(const float4*)&g_tmp[ib + f0];
    float4 t1 = *(const float4*)&g_tmp[ib + f1];
    float4 v0 = *(const float4*)&g_vsum[(b * NH + h0) * DIM + (f0 & 127)];
    float4 v1 = *(const float4*)&g_vsum[(b * NH + h1) * DIM + (f1 & 127)];

    float4 r0, r1;
    r0.x = 0.5f*gg0.x + 0.5f*((t0.x + v0.x) * id0);
    r0.y = 0.5f*gg0.y + 0.5f*((t0.y + v0.y) * id0);
    r0.z = 0.5f*gg0.z + 0.5f*((t0.z + v0.z) * id0);
    r0.w = 0.5f*gg0.w + 0.5f*((t0.w + v0.w) * id0);
    r1.x = 0.5f*gg1.x + 0.5f*((t1.x + v1.x) * id1);
    r1.y = 0.5f*gg1.y + 0.5f*((t1.y + v1.y) * id1);
    r1.z = 0.5f*gg1.z + 0.5f*((t1.z + v1.z) * id1);
    r1.w = 0.5f*gg1.w + 0.5f*((t1.w + v1.w) * id1);

    *(float4*)&curn[ib + f0] = r0;
    *(float4*)&curn[ib + f1] = r1;

    float4 a0 = *(float4*)&g_acc[ib + f0];
    a0.x += r0.x; a0.y += r0.y; a0.z += r0.z; a0.w += r0.w;
    *(float4*)&g_acc[ib + f0] = a0;
    float4 a1 = *(float4*)&g_acc[ib + f1];
    a1.x += r1.x; a1.y += r1.y; a1.z += r1.z; a1.w += r1.w;
    *(float4*)&g_acc[ib + f1] = a1;
}

// ----------------------------- host orchestration ----------------------------
extern "C" void kernel_launch(void* const* d_in, const int* in_sizes, int n_in,
                              void* d_out, int out_size)
{
    const float* x    = (const float*)d_in[0];
    const float* Wq_w = (const float*)d_in[1];
    const float* Wq_b = (const float*)d_in[2];
    const float* Wk_w = (const float*)d_in[3];
    const float* Wk_b = (const float*)d_in[4];
    const float* Wo_w = (const float*)d_in[5];
    const float* Wo_b = (const float*)d_in[6];
    const int*   ei   = (const int*)  d_in[7];
    float* out = (float*)d_out;

    float *qs, *ks, *cur0, *cur1, *acc, *tmp, *kvt, *pkv, *pv, *vsum, *ksp, *ksum;
    int *cnt, *fill;
    cudaGetSymbolAddress((void**)&qs,   g_qs);
    cudaGetSymbolAddress((void**)&ks,   g_ks);
    cudaGetSymbolAddress((void**)&cur0, g_cur0);
    cudaGetSymbolAddress((void**)&cur1, g_cur1);
    cudaGetSymbolAddress((void**)&acc,  g_acc);
    cudaGetSymbolAddress((void**)&tmp,  g_tmp);
    cudaGetSymbolAddress((void**)&kvt,  g_kvt);
    cudaGetSymbolAddress((void**)&pkv,  g_pkv);
    cudaGetSymbolAddress((void**)&pv,   g_pv);
    cudaGetSymbolAddress((void**)&vsum, g_vsum);
    cudaGetSymbolAddress((void**)&ksp,  g_ksp);
    cudaGetSymbolAddress((void**)&ksum, g_ksum);
    cudaGetSymbolAddress((void**)&cnt,  g_cnt);
    cudaGetSymbolAddress((void**)&fill, g_fill);

    // Q/K projections: [32768,512] = x[32768,128] @ W^T + b
    gemm_abT<<<dim3(256,4,1),256>>>(x, DIM, 0, 0, Wq_w, DIM, 0, 0, Wq_b, qs, HD, 0, 0, DIM, 1.f);
    gemm_abT<<<dim3(256,4,1),256>>>(x, DIM, 0, 0, Wk_w, DIM, 0, 0, Wk_b, ks, HD, 0, 0, DIM, 1.f);
    normalize_qk_kernel<<<NNODES,128>>>();
    ksum_partial_kernel<<<dim3(NCH,32),128>>>();
    reduce16<<<16,256>>>(ksp, ksum, 4096);
    invden_kernel<<<NNODES,128>>>();

    // Graph prep: degrees, CSR, normalized weights (deterministic order)
    cudaMemsetAsync(cnt,  0, NNODES * sizeof(int));
    cudaMemsetAsync(fill, 0, NNODES * sizeof(int));
    count_kernel<<<NEDGE/256,256>>>(ei);
    scan1_kernel<<<NNODES/256,256>>>();
    scan2_kernel<<<1,128>>>();
    scan3_kernel<<<NNODES/256,256>>>();
    scatter_kernel<<<NEDGE/256,256>>>(ei);
    sortw_kernel<<<NNODES/128,128>>>();

    // cur = acc = broadcast(x) over heads
    init_kernel<<<16384,256>>>(x);

    float* curA = cur0; float* curB = cur1;
    for (int it = 0; it < 4; it++) {
        kv_partial_kernel<<<dim3(NCH,32),256>>>(curA);
        reduce16<<<2048,256>>>(pkv, kvt, 32*16384);
        reduce16<<<16,256>>>(pv, vsum, 4096);
        // tmp[n, h*128+e] = qs[n, h*128+:] @ KV  (batched over 32 (b,h))
        gemm_abT<<<dim3(32,1,32),256>>>(qs, HD, (long)NPG*HD, DIM,
                                        kvt, DIM, 4L*16384, 16384,
                                        nullptr,
                                        tmp, HD, (long)NPG*HD, DIM,
                                        DIM, 1.f);
        fuse_kernel<<<NNODES/4,256>>>(curA, curB);
        float* sw = curA; curA = curB; curB = sw;
    }

    // out = (acc @ Wo^T + Wo_b) / H
    gemm_abT<<<dim3(256,1,1),256>>>(acc, HD, 0, 0, Wo_w, HD, 0, 0, Wo_b,
                                    out, DIM, 0, 0, HD, 0.25f);
    (void)in_sizes; (void)n_in; (void)out_size;
}

// round 7
// speedup vs baseline: 1.7812x; 1.7803x over previous
#include <cuda_runtime.h>
#include <cstdint>

// Problem constants (fixed by setup_inputs)
#define NNODES 32768
#define DIM    128
#define NH     4
#define HD     512      // NH*DIM
#define NEDGE  262144
#define NGRAPH 8
#define NPG    4096
#define NCH    16       // chunks per (b,h) for KV partials
#define CHN    256      // nodes per chunk (NPG/NCH)

// ----------------------------- scratch (static device globals) ---------------
__device__ float g_qs  [NNODES*HD];
__device__ float g_ks  [NNODES*HD];
__device__ float g_cur0[NNODES*HD];
__device__ float g_cur1[NNODES*HD];
__device__ float g_acc [NNODES*HD];
__device__ float g_tmp [NNODES*HD];
__device__ float g_kvt [32*16384];        // KV^T per (b,h): [e][d]
__device__ float g_pkv [NCH*32*16384];    // KV partials per chunk
__device__ float g_pv  [NCH*4096];        // vsum partials
__device__ float g_vsum[4096];
__device__ float g_ksp [NCH*4096];        // ksum partials
__device__ float g_ksum[4096];
__device__ float g_invden[NNODES*NH];
__device__ float g_dis [NNODES];
__device__ float g_w   [NEDGE];
__device__ int   g_cnt [NNODES];
__device__ int   g_rowptr[NNODES+1];
__device__ int   g_fill[NNODES];
__device__ int   g_bsum[NNODES/256];
__device__ int   g_col [NEDGE];
__device__ int   g_ekey[NEDGE];

// ----------------------------- TF32 helpers ----------------------------------
__device__ __forceinline__ uint32_t tf32r(float x) {
    uint32_t u;
    asm("cvt.rna.tf32.f32 %0, %1;" : "=r"(u) : "f"(x));
    return u;
}

#define MMA_TF32(cc, aa, b0v, b1v)                                              \
    asm volatile("mma.sync.aligned.m16n8k8.row.col.f32.tf32.tf32.f32 "          \
                 "{%0,%1,%2,%3}, {%4,%5,%6,%7}, {%8,%9}, {%0,%1,%2,%3};"        \
                 : "+f"((cc)[0]), "+f"((cc)[1]), "+f"((cc)[2]), "+f"((cc)[3])   \
                 : "r"((aa)[0]), "r"((aa)[1]), "r"((aa)[2]), "r"((aa)[3]),      \
                   "r"(b0v), "r"(b1v))

// ----------------------------- tensor-core GEMM: C = scale*(A*B^T + bias) ----
// A[M,K] lda, B[Nc,K] ldb (row-major), C[M,Nc] ldc. 128x128 tile per block,
// 256 threads (8 warps, 4x2), each warp 32x64 via m16n8k8 tf32 MMA.
// Batched over blockIdx.z with (b,h) split strides.
__global__ void gemm_abT_tc(const float* __restrict__ A, int lda, long sOutA, long sInA,
                            const float* __restrict__ Bm, int ldb, long sOutB, long sInB,
                            const float* __restrict__ bias,
                            float* __restrict__ C, int ldc, long sOutC, long sInC,
                            int K, float scale)
{
    __shared__ uint32_t As[128][40];   // [m][k], pitch 40 (8 mod 32) -> conflict-free frag LDS
    __shared__ uint32_t Bs[128][40];   // [n][k]
    int z = blockIdx.z; int zb = z >> 2, zh = z & 3;
    const float* Ab = A  + zb*sOutA + zh*sInA;
    const float* Bb = Bm + zb*sOutB + zh*sInB;
    float*       Cb = C  + zb*sOutC + zh*sInC;
    int i0 = blockIdx.x * 128, j0 = blockIdx.y * 128;
    int tid = threadIdx.x;
    int wid = tid >> 5, lane = tid & 31;
    int g = lane >> 2, t = lane & 3;
    int mbase = (wid & 3) * 32, nbase = (wid >> 2) * 64;

    float c[2][8][4];
#pragma unroll
    for (int mt = 0; mt < 2; mt++)
#pragma unroll
        for (int nt = 0; nt < 8; nt++)
#pragma unroll
            for (int q = 0; q < 4; q++) c[mt][nt][q] = 0.f;

    for (int kt = 0; kt < K; kt += 32) {
#pragma unroll
        for (int r = 0; r < 4; r++) {
            int idx = tid + r * 256;         // 0..1023
            int row = idx >> 3;              // 0..127
            int kq  = (idx & 7) << 2;        // 0..28
            float4 v = *(const float4*)&Ab[(long)(i0 + row) * lda + kt + kq];
            As[row][kq+0] = tf32r(v.x); As[row][kq+1] = tf32r(v.y);
            As[row][kq+2] = tf32r(v.z); As[row][kq+3] = tf32r(v.w);
            float4 w = *(const float4*)&Bb[(long)(j0 + row) * ldb + kt + kq];
            Bs[row][kq+0] = tf32r(w.x); Bs[row][kq+1] = tf32r(w.y);
            Bs[row][kq+2] = tf32r(w.z); Bs[row][kq+3] = tf32r(w.w);
        }
        __syncthreads();
#pragma unroll
        for (int ks = 0; ks < 4; ks++) {
            int k0 = ks * 8;
            uint32_t a[2][4];
#pragma unroll
            for (int mt = 0; mt < 2; mt++) {
                int m = mbase + mt * 16 + g;
                a[mt][0] = As[m    ][k0 + t];
                a[mt][1] = As[m + 8][k0 + t];
                a[mt][2] = As[m    ][k0 + t + 4];
                a[mt][3] = As[m + 8][k0 + t + 4];
            }
#pragma unroll
            for (int nt = 0; nt < 8; nt++) {
                int n = nbase + nt * 8 + g;
                uint32_t b0 = Bs[n][k0 + t];
                uint32_t b1 = Bs[n][k0 + t + 4];
                MMA_TF32(c[0][nt], a[0], b0, b1);
                MMA_TF32(c[1][nt], a[1], b0, b1);
            }
        }
        __syncthreads();
    }
#pragma unroll
    for (int mt = 0; mt < 2; mt++) {
        int r0 = i0 + mbase + mt * 16 + g;
#pragma unroll
        for (int nt = 0; nt < 8; nt++) {
            int col = j0 + nbase + nt * 8 + 2 * t;
            float b0 = bias ? bias[col]     : 0.f;
            float b1 = bias ? bias[col + 1] : 0.f;
            float2 o;
            o.x = scale * (c[mt][nt][0] + b0);
            o.y = scale * (c[mt][nt][1] + b1);
            *(float2*)&Cb[(long)r0 * ldc + col] = o;
            o.x = scale * (c[mt][nt][2] + b0);
            o.y = scale * (c[mt][nt][3] + b1);
            *(float2*)&Cb[(long)(r0 + 8) * ldc + col] = o;
        }
    }
}

// ----------------------------- normalize q,k rows per (node, head) -----------
__global__ void normalize_qk_kernel()
{
    int i = blockIdx.x;
    int h = threadIdx.x >> 5, l = threadIdx.x & 31;
    long base = (long)i * HD + h * DIM + l * 4;
    float4 q = *(float4*)&g_qs[base];
    float s = q.x*q.x + q.y*q.y + q.z*q.z + q.w*q.w;
#pragma unroll
    for (int o = 16; o; o >>= 1) s += __shfl_xor_sync(0xffffffffu, s, o);
    float r = rsqrtf(s);
    q.x *= r; q.y *= r; q.z *= r; q.w *= r;
    *(float4*)&g_qs[base] = q;

    float4 k = *(float4*)&g_ks[base];
    s = k.x*k.x + k.y*k.y + k.z*k.z + k.w*k.w;
#pragma unroll
    for (int o = 16; o; o >>= 1) s += __shfl_xor_sync(0xffffffffu, s, o);
    r = rsqrtf(s);
    k.x *= r; k.y *= r; k.z *= r; k.w *= r;
    *(float4*)&g_ks[base] = k;
}

// ----------------------------- ksum partials ---------------------------------
__global__ void ksum_partial_kernel()
{
    int chunk = blockIdx.x, bh = blockIdx.y;
    int b = bh >> 2, h = bh & 3, d = threadIdx.x;
    long base = ((long)b * NPG + chunk * CHN) * HD + h * DIM + d;
    float s = 0.f;
    for (int n = 0; n < CHN; n++) s += g_ks[base + (long)n * HD];
    g_ksp[(chunk * 32 + bh) * DIM + d] = s;
}

// deterministic fixed-order reduce of 16 chunk partials
__global__ void reduce16(const float* __restrict__ part, float* __restrict__ out, int n)
{
    int i = blockIdx.x * blockDim.x + threadIdx.x;
    if (i < n) {
        float s = 0.f;
#pragma unroll
        for (int c = 0; c < NCH; c++) s += part[(long)c * n + i];
        out[i] = s;
    }
}

// ----------------------------- inverse denominator (loop-invariant) ----------
__global__ void invden_kernel()
{
    int i = blockIdx.x;
    int h = threadIdx.x >> 5, l = threadIdx.x & 31;
    int b = i >> 12;  // /NPG
    float4 q = *(float4*)&g_qs[(long)i * HD + h * DIM + l * 4];
    float4 km = *(float4*)&g_ksum[(b * NH + h) * DIM + l * 4];
    float s = q.x*km.x + q.y*km.y + q.z*km.z + q.w*km.w;
#pragma unroll
    for (int o = 16; o; o >>= 1) s += __shfl_xor_sync(0xffffffffu, s, o);
    if (l == 0) g_invden[i * NH + h] = 1.f / (s + (float)NPG);
}

// ----------------------------- graph prep ------------------------------------
__global__ void count_kernel(const int* __restrict__ ei)
{
    int e = blockIdx.x * blockDim.x + threadIdx.x;
    if (e < NEDGE) atomicAdd(&g_cnt[ei[e]], 1);
}

__global__ void scan1_kernel()
{
    __shared__ int sh[256];
    int tid = threadIdx.x;
    int i = blockIdx.x * 256 + tid;
    int v = g_cnt[i];
    sh[tid] = v;
    __syncthreads();
    for (int o = 1; o < 256; o <<= 1) {
        int t = (tid >= o) ? sh[tid - o] : 0;
        __syncthreads();
        sh[tid] += t;
        __syncthreads();
    }
    g_rowptr[i] = sh[tid] - v;                 // block-local exclusive
    if (tid == 255) g_bsum[blockIdx.x] = sh[255];
}

__global__ void scan2_kernel()
{
    __shared__ int sh[128];
    int tid = threadIdx.x;
    int v = g_bsum[tid];
    sh[tid] = v;
    __syncthreads();
    for (int o = 1; o < 128; o <<= 1) {
        int t = (tid >= o) ? sh[tid - o] : 0;
        __syncthreads();
        sh[tid] += t;
        __syncthreads();
    }
    g_bsum[tid] = sh[tid] - v;                 // exclusive block offsets
}

__global__ void scan3_kernel()
{
    int tid = threadIdx.x;
    int i = blockIdx.x * 256 + tid;
    g_rowptr[i] += g_bsum[blockIdx.x];
    int c = g_cnt[i];
    g_dis[i] = (c > 0) ? rsqrtf((float)c) : 0.f;
    if (i == 0) g_rowptr[NNODES] = NEDGE;
}

__global__ void scatter_kernel(const int* __restrict__ ei)
{
    int e = blockIdx.x * blockDim.x + threadIdx.x;
    if (e < NEDGE) {
        int r = ei[e], c = ei[NEDGE + e];
        int p = g_rowptr[r] + atomicAdd(&g_fill[r], 1);
        g_col[p] = c;
        g_ekey[p] = e;
    }
}

// canonicalize per-row edge order (determinism) + edge weights
__global__ void sortw_kernel()
{
    int i = blockIdx.x * blockDim.x + threadIdx.x;
    if (i >= NNODES) return;
    int s = g_rowptr[i], t = g_rowptr[i + 1];
    int n = t - s;
    float di = g_dis[i];
    if (n > 1 && n <= 64) {
        int kk[64], cc[64];
        for (int j = 0; j < n; j++) { kk[j] = g_ekey[s + j]; cc[j] = g_col[s + j]; }
        for (int a = 1; a < n; a++) {
            int kvv = kk[a], cv = cc[a], b = a - 1;
            while (b >= 0 && kk[b] > kvv) { kk[b+1] = kk[b]; cc[b+1] = cc[b]; b--; }
            kk[b+1] = kvv; cc[b+1] = cv;
        }
        for (int j = 0; j < n; j++) { g_col[s + j] = cc[j]; g_w[s + j] = di * g_dis[cc[j]]; }
    } else {
        for (int j = 0; j < n; j++) g_w[s + j] = di * g_dis[g_col[s + j]];
    }
}

// ----------------------------- init cur = acc = broadcast(x) -----------------
__global__ void init_kernel(const float* __restrict__ x)
{
    long gid = (long)blockIdx.x * blockDim.x + threadIdx.x;  // float4 index
    long f = gid * 4;
    int i = (int)(f >> 9);
    int d = (int)(f & 127);
    float4 v = *(const float4*)&x[(long)i * DIM + d];
    *(float4*)&g_cur0[f] = v;
    *(float4*)&g_acc[f]  = v;
}

// ----------------------------- per-iter: KV^T partials + vsum (tensor core) --
// C[e,d] = sum_n cur[n,e]*ks[n,d] over a 256-node chunk; vsum partial in fp32.
__global__ void kv_partial_tc(const float* __restrict__ cur)
{
    __shared__ uint32_t CU[32][136];   // [node][e], pitch 136 (8 mod 32)
    __shared__ uint32_t KS[32][136];   // [node][d]
    int chunk = blockIdx.x, bh = blockIdx.y;
    int b = bh >> 2, h = bh & 3;
    long nodeBase = (long)b * NPG + chunk * CHN;
    int tid = threadIdx.x;
    int wid = tid >> 5, lane = tid & 31;
    int g = lane >> 2, t = lane & 3;
    int mbase = (wid & 3) * 32, nbase = (wid >> 2) * 64;

    float c[2][8][4];
#pragma unroll
    for (int mt = 0; mt < 2; mt++)
#pragma unroll
        for (int nt = 0; nt < 8; nt++)
#pragma unroll
            for (int q = 0; q < 4; q++) c[mt][nt][q] = 0.f;
    float4 vs = make_float4(0.f, 0.f, 0.f, 0.f);

    for (int t0 = 0; t0 < CHN; t0 += 32) {
#pragma unroll
        for (int r = 0; r < 4; r++) {
            int idx = tid + r * 256;          // 0..1023
            int nn = idx >> 5;                // 0..31
            int c4 = (idx & 31) * 4;          // 0..124
            long off = (nodeBase + t0 + nn) * HD + h * DIM + c4;
            float4 u  = *(const float4*)&cur[off];
            float4 k4 = *(const float4*)&g_ks[off];
            vs.x += u.x; vs.y += u.y; vs.z += u.z; vs.w += u.w;
            CU[nn][c4+0] = tf32r(u.x);  CU[nn][c4+1] = tf32r(u.y);
            CU[nn][c4+2] = tf32r(u.z);  CU[nn][c4+3] = tf32r(u.w);
            KS[nn][c4+0] = tf32r(k4.x); KS[nn][c4+1] = tf32r(k4.y);
            KS[nn][c4+2] = tf32r(k4.z); KS[nn][c4+3] = tf32r(k4.w);
        }
        __syncthreads();
#pragma unroll
        for (int ks = 0; ks < 4; ks++) {
            int k0 = ks * 8;
            uint32_t a[2][4];
#pragma unroll
            for (int mt = 0; mt < 2; mt++) {
                int m = mbase + mt * 16 + g;
                a[mt][0] = CU[k0 + t    ][m];
                a[mt][1] = CU[k0 + t    ][m + 8];
                a[mt][2] = CU[k0 + t + 4][m];
                a[mt][3] = CU[k0 + t + 4][m + 8];
            }
#pragma unroll
            for (int nt = 0; nt < 8; nt++) {
                int n = nbase + nt * 8 + g;
                uint32_t b0 = KS[k0 + t    ][n];
                uint32_t b1 = KS[k0 + t + 4][n];
                MMA_TF32(c[0][nt], a[0], b0, b1);
                MMA_TF32(c[1][nt], a[1], b0, b1);
            }
        }
        __syncthreads();
    }

    // vsum staging: thread owns column (tid&31)*4, replicated over tid>>5
    {
        int cb = (tid & 31) * 4, rv = tid >> 5;
        CU[rv][cb+0] = __float_as_uint(vs.x);
        CU[rv][cb+1] = __float_as_uint(vs.y);
        CU[rv][cb+2] = __float_as_uint(vs.z);
        CU[rv][cb+3] = __float_as_uint(vs.w);
    }
    __syncthreads();
    if (tid < 128) {
        float s = 0.f;
#pragma unroll
        for (int j = 0; j < 8; j++) s += __uint_as_float(CU[j][tid]);
        g_pv[(chunk * 32 + bh) * 128 + tid] = s;
    }

    long base = ((long)chunk * 32 + bh) * 16384;
#pragma unroll
    for (int mt = 0; mt < 2; mt++) {
        int r0 = mbase + mt * 16 + g;
#pragma unroll
        for (int nt = 0; nt < 8; nt++) {
            int col = nbase + nt * 8 + 2 * t;
            float2 o;
            o.x = c[mt][nt][0]; o.y = c[mt][nt][1];
            *(float2*)&g_pkv[base + (long)r0 * 128 + col] = o;
            o.x = c[mt][nt][2]; o.y = c[mt][nt][3];
            *(float2*)&g_pkv[base + (long)(r0 + 8) * 128 + col] = o;
        }
    }
}

// ----------------------------- per-iter: GCN gather + attn combine + acc -----
__global__ void fuse_kernel(const float* __restrict__ cur, float* __restrict__ curn)
{
    int slot = threadIdx.x >> 6;       // 4 nodes per block
    int t = threadIdx.x & 63;          // 64 threads per node
    int i = blockIdx.x * 4 + slot;
    int b = i >> 12;
    int f0 = t * 4, f1 = t * 4 + 256;
    int s = g_rowptr[i], e = g_rowptr[i + 1];

    float4 gg0 = make_float4(0,0,0,0), gg1 = make_float4(0,0,0,0);
    for (int p = s; p < e; p++) {
        int c = g_col[p]; float w = g_w[p];
        const float* cr = cur + (long)c * HD;
        float4 a0 = *(const float4*)&cr[f0];
        float4 a1 = *(const float4*)&cr[f1];
        gg0.x += w * a0.x; gg0.y += w * a0.y; gg0.z += w * a0.z; gg0.w += w * a0.w;
        gg1.x += w * a1.x; gg1.y += w * a1.y; gg1.z += w * a1.z; gg1.w += w * a1.w;
    }
    int h0 = f0 >> 7, h1 = f1 >> 7;
    float id0 = g_invden[i * NH + h0];
    float id1 = g_invden[i * NH + h1];
    long ib = (long)i * HD;
    float4 t0 = *(const float4*)&g_tmp[ib + f0];
    float4 t1 = *(const float4*)&g_tmp[ib + f1];
    float4 v0 = *(const float4*)&g_vsum[(b * NH + h0) * DIM + (f0 & 127)];
    float4 v1 = *(const float4*)&g_vsum[(b * NH + h1) * DIM + (f1 & 127)];

    float4 r0, r1;
    r0.x = 0.5f*gg0.x + 0.5f*((t0.x + v0.x) * id0);
    r0.y = 0.5f*gg0.y + 0.5f*((t0.y + v0.y) * id0);
    r0.z = 0.5f*gg0.z + 0.5f*((t0.z + v0.z) * id0);
    r0.w = 0.5f*gg0.w + 0.5f*((t0.w + v0.w) * id0);
    r1.x = 0.5f*gg1.x + 0.5f*((t1.x + v1.x) * id1);
    r1.y = 0.5f*gg1.y + 0.5f*((t1.y + v1.y) * id1);
    r1.z = 0.5f*gg1.z + 0.5f*((t1.z + v1.z) * id1);
    r1.w = 0.5f*gg1.w + 0.5f*((t1.w + v1.w) * id1);

    *(float4*)&curn[ib + f0] = r0;
    *(float4*)&curn[ib + f1] = r1;

    float4 a0 = *(float4*)&g_acc[ib + f0];
    a0.x += r0.x; a0.y += r0.y; a0.z += r0.z; a0.w += r0.w;
    *(float4*)&g_acc[ib + f0] = a0;
    float4 a1 = *(float4*)&g_acc[ib + f1];
    a1.x += r1.x; a1.y += r1.y; a1.z += r1.z; a1.w += r1.w;
    *(float4*)&g_acc[ib + f1] = a1;
}

// ----------------------------- host orchestration ----------------------------
extern "C" void kernel_launch(void* const* d_in, const int* in_sizes, int n_in,
                              void* d_out, int out_size)
{
    const float* x    = (const float*)d_in[0];
    const float* Wq_w = (const float*)d_in[1];
    const float* Wq_b = (const float*)d_in[2];
    const float* Wk_w = (const float*)d_in[3];
    const float* Wk_b = (const float*)d_in[4];
    const float* Wo_w = (const float*)d_in[5];
    const float* Wo_b = (const float*)d_in[6];
    const int*   ei   = (const int*)  d_in[7];
    float* out = (float*)d_out;

    float *qs, *ks, *cur0, *cur1, *acc, *tmp, *kvt, *pkv, *pv, *vsum, *ksp, *ksum;
    int *cnt, *fill;
    cudaGetSymbolAddress((void**)&qs,   g_qs);
    cudaGetSymbolAddress((void**)&ks,   g_ks);
    cudaGetSymbolAddress((void**)&cur0, g_cur0);
    cudaGetSymbolAddress((void**)&cur1, g_cur1);
    cudaGetSymbolAddress((void**)&acc,  g_acc);
    cudaGetSymbolAddress((void**)&tmp,  g_tmp);
    cudaGetSymbolAddress((void**)&kvt,  g_kvt);
    cudaGetSymbolAddress((void**)&pkv,  g_pkv);
    cudaGetSymbolAddress((void**)&pv,   g_pv);
    cudaGetSymbolAddress((void**)&vsum, g_vsum);
    cudaGetSymbolAddress((void**)&ksp,  g_ksp);
    cudaGetSymbolAddress((void**)&ksum, g_ksum);
    cudaGetSymbolAddress((void**)&cnt,  g_cnt);
    cudaGetSymbolAddress((void**)&fill, g_fill);

    // Q/K projections: [32768,512] = x[32768,128] @ W^T + b (tensor core tf32)
    gemm_abT_tc<<<dim3(256,4,1),256>>>(x, DIM, 0, 0, Wq_w, DIM, 0, 0, Wq_b, qs, HD, 0, 0, DIM, 1.f);
    gemm_abT_tc<<<dim3(256,4,1),256>>>(x, DIM, 0, 0, Wk_w, DIM, 0, 0, Wk_b, ks, HD, 0, 0, DIM, 1.f);
    normalize_qk_kernel<<<NNODES,128>>>();
    ksum_partial_kernel<<<dim3(NCH,32),128>>>();
    reduce16<<<16,256>>>(ksp, ksum, 4096);
    invden_kernel<<<NNODES,128>>>();

    // Graph prep: degrees, CSR, normalized weights (deterministic order)
    cudaMemsetAsync(cnt,  0, NNODES * sizeof(int));
    cudaMemsetAsync(fill, 0, NNODES * sizeof(int));
    count_kernel<<<NEDGE/256,256>>>(ei);
    scan1_kernel<<<NNODES/256,256>>>();
    scan2_kernel<<<1,128>>>();
    scan3_kernel<<<NNODES/256,256>>>();
    scatter_kernel<<<NEDGE/256,256>>>(ei);
    sortw_kernel<<<NNODES/128,128>>>();

    // cur = acc = broadcast(x) over heads
    init_kernel<<<16384,256>>>(x);

    float* curA = cur0; float* curB = cur1;
    for (int it = 0; it < 4; it++) {
        kv_partial_tc<<<dim3(NCH,32),256>>>(curA);
        reduce16<<<2048,256>>>(pkv, kvt, 32*16384);
        reduce16<<<16,256>>>(pv, vsum, 4096);
        // tmp[n, h*128+e] = qs[n, h*128+:] @ KV  (batched over 32 (b,h))
        gemm_abT_tc<<<dim3(32,1,32),256>>>(qs, HD, (long)NPG*HD, DIM,
                                           kvt, DIM, 4L*16384, 16384,
                                           nullptr,
                                           tmp, HD, (long)NPG*HD, DIM,
                                           DIM, 1.f);
        fuse_kernel<<<NNODES/4,256>>>(curA, curB);
        float* sw = curA; curA = curB; curB = sw;
    }

    // out = (acc @ Wo^T + Wo_b) / H
    gemm_abT_tc<<<dim3(256,1,1),256>>>(acc, HD, 0, 0, Wo_w, HD, 0, 0, Wo_b,
                                       out, DIM, 0, 0, HD, 0.25f);
    (void)in_sizes; (void)n_in; (void)out_size;
}